// round 10
// baseline (speedup 1.0000x reference)
#include <cuda_runtime.h>
#include <cuda_bf16.h>
#include <math.h>
#include <stdint.h>

#define B_  16
#define C_  128
#define O_  256
#define H_  96
#define W_  96
#define KH  5
#define HO  92
#define WO  92
#define HW_IN  (H_*W_)        // 9216
#define HW_OUT (HO*WO)        // 8464
#define KK  25
#define NPT 67                // ceil(8464/128)
#define NSTAGE 100            // 25 taps * 4 k32-chunks

// ---------------- device scratch (no allocation allowed) ----------------
__device__ __align__(128) __nv_bfloat16 g_Ah[(size_t)2*B_*HW_IN*128];
__device__ __align__(128) __nv_bfloat16 g_Al[(size_t)B_*HW_IN*128];
// Weights: [path][og][tap][split][o_local(128)][c(128)]; path1 uses split 0 only
__device__ __align__(128) __nv_bfloat16 g_Wp[(size_t)2*2*KK*2*16384];
__device__ float g_Tp[2*B_*HW_IN];
__device__ float g_S [B_*HW_OUT];
__device__ float g_sp[O_];

// ---------------- PTX helpers ----------------
__device__ __forceinline__ uint32_t smem_u32(const void* p){
    return (uint32_t)__cvta_generic_to_shared((void*)p);
}
__device__ __forceinline__ void cp16(uint32_t dst, const void* src){
    asm volatile("cp.async.cg.shared.global [%0], [%1], 16;\n" :: "r"(dst), "l"(src));
}
__device__ __forceinline__ void cp_commit(){ asm volatile("cp.async.commit_group;\n" ::: "memory"); }
template<int N> __device__ __forceinline__ void cp_wait(){
    asm volatile("cp.async.wait_group %0;\n" :: "n"(N) : "memory");
}
__device__ __forceinline__ void ldsm4(uint32_t* r, uint32_t addr){
    asm volatile("ldmatrix.sync.aligned.m8n8.x4.shared.b16 {%0,%1,%2,%3}, [%4];"
        : "=r"(r[0]), "=r"(r[1]), "=r"(r[2]), "=r"(r[3]) : "r"(addr));
}
#define MMA(acc, a, b0, b1)                                                        \
    asm volatile("mma.sync.aligned.m16n8k16.row.col.f32.bf16.bf16.f32 "            \
                 "{%0,%1,%2,%3},{%4,%5,%6,%7},{%8,%9},{%0,%1,%2,%3};"              \
                 : "+f"((acc)[0]), "+f"((acc)[1]), "+f"((acc)[2]), "+f"((acc)[3])  \
                 : "r"((a)[0]), "r"((a)[1]), "r"((a)[2]), "r"((a)[3]),             \
                   "r"(b0), "r"(b1))

// ---------------- prep kernels ----------------
__global__ void transpose_split_kernel(const float* __restrict__ mu,
                                       const float* __restrict__ sg) {
    __shared__ float ts[C_][65];
    int pt = blockIdx.x, b = blockIdx.y, path = blockIdx.z;
    const float* src = (path ? sg : mu) + (size_t)b * C_ * HW_IN + pt * 64;
    int tid = threadIdx.x;
    for (int i = tid; i < C_ * 64; i += 256) {
        int c = i >> 6, pi = i & 63;
        ts[c][pi] = src[(size_t)c * HW_IN + pi];
    }
    __syncthreads();
    size_t obase = (size_t)(path * B_ + b) * HW_IN * 128;
    int p0 = pt * 64;
    for (int i = tid; i < 64 * C_; i += 256) {
        int pi = i >> 7, c = i & 127;
        float v = ts[c][pi];
        __nv_bfloat16 hi = __float2bfloat16(v);
        size_t idx = obase + (size_t)(p0 + pi) * 128 + c;
        g_Ah[idx] = hi;
        if (path == 0)
            g_Al[(size_t)b * HW_IN * 128 + (size_t)(p0 + pi) * 128 + c] =
                __float2bfloat16(v - __bfloat162float(hi));
    }
    if (tid < 64) {
        float acc = 0.0f;
        #pragma unroll 8
        for (int c = 0; c < C_; ++c) {
            float v = ts[c][tid];
            acc += path ? v : v * v;
        }
        g_Tp[(size_t)(path * B_ + b) * HW_IN + p0 + tid] = acc;
    }
}

__global__ void wprep_kernel(const float* __restrict__ W,
                             const float* __restrict__ w_sigma) {
    int gid = blockIdx.x * blockDim.x + threadIdx.x;
    if (gid < O_) {
        float w = fmaxf(w_sigma[gid], -88.0f);
        g_sp[gid] = log1pf(expf(w));
    }
    if (gid >= O_ * C_) return;
    int o = gid >> 7, c = gid & 127;
    int og = o >> 7, ol = o & 127;
    const float* wp = W + ((size_t)o * C_ + c) * KK;
    int dst_in = ol * 128 + c;
    #pragma unroll
    for (int tap = 0; tap < KK; ++tap) {
        float w  = wp[tap];
        float w2 = w * w;
        __nv_bfloat16 h0 = __float2bfloat16(w);
        __nv_bfloat16 l0 = __float2bfloat16(w  - __bfloat162float(h0));
        size_t blk0 = (size_t)(((0 * 2 + og) * KK + tap) * 2);
        size_t blk1 = (size_t)(((1 * 2 + og) * KK + tap) * 2);
        g_Wp[(blk0 + 0) * 16384 + dst_in] = h0;
        g_Wp[(blk0 + 1) * 16384 + dst_in] = l0;
        g_Wp[(blk1 + 0) * 16384 + dst_in] = __float2bfloat16(w2);
    }
}

__global__ void boxsum_kernel() {
    int i = blockIdx.x * blockDim.x + threadIdx.x;
    if (i >= B_*HW_OUT) return;
    int b = i / HW_OUT;
    int p = i - b * HW_OUT;
    int y = p / WO;
    int x = p - y * WO;
    const float* t0 = g_Tp + (size_t)b * HW_IN;
    const float* t1 = g_Tp + (size_t)(B_ + b) * HW_IN;
    float acc = 0.0f;
    #pragma unroll
    for (int dy = 0; dy < KH; ++dy)
        #pragma unroll
        for (int dx = 0; dx < KH; ++dx) {
            int off = (y + dy) * W_ + (x + dx);
            acc += t0[off] + t1[off];
        }
    g_S[i] = acc;
}

// ---------------- main mma.sync conv: k32 stages, ring-3, 2 CTA/SM ----------------
// Buffer (32KB): Ah 8K | Al 8K | Bh 8K | Bl 8K. Ring of 3 = 96KB. path1 uses Ah/Bh.
// 64B k32 rows packed in pairs per 128B line, swizzle: (row>>1)*128 + (row&1)*64
//   + ((chunk ^ ((row>>1)&3))<<4)  -> conflict-free ldmatrix phases.
// Warp de-phasing: warp w processes k-slices in order ks = ksi ^ (wid&1) so that
// at any instant half the warps are in ldsm (LSU) and half in MMA (tensor),
// instead of the barrier phase-aligning all warps into alternating bursts.
#define BUFSZ   32768u
#define OFF_AL  8192u
#define OFF_BH  16384u
#define OFF_BL  24576u
#define SMEM_MAIN 98304

__global__ void __launch_bounds__(256, 2)
mma_conv_kernel(const float* __restrict__ bias, float* __restrict__ out) {
    extern __shared__ char smem[];
    uint32_t sb = smem_u32(smem);
    int tid = threadIdx.x;
    int lane = tid & 31, wid = tid >> 5;
    int warp_m = wid >> 2, warp_n = wid & 3;

    int ptile = blockIdx.x, b = blockIdx.y;
    int path = blockIdx.z & 1, og = blockIdx.z >> 1;

    // ---- staging setup ----
    int m_pix = tid & 127;
    int p  = ptile * 128 + m_pix;
    int pc = min(p, HW_OUT - 1);
    int py = pc / WO, px = pc - py * WO;
    const __nv_bfloat16* aplane =
        (tid < 128 ? g_Ah + (size_t)(path * B_ + b) * HW_IN * 128
                   : g_Al + (size_t)b * HW_IN * 128);
    uint32_t a_sm_base = (tid < 128 ? 0u : OFF_AL)
                       + (uint32_t)((m_pix >> 1) * 128 + (m_pix & 1) * 64);
    int aq = (m_pix >> 1) & 3;

    int br = tid >> 1;                       // weight row 0..127
    const char* wblk = (const char*)g_Wp +
        (size_t)((path * 2 + og) * KK) * 2 * 32768;
    uint32_t b_sm_base = OFF_BH + (uint32_t)((br >> 1) * 128 + (br & 1) * 64);
    int bq = (br >> 1) & 3;

    auto stage = [&](int s, int buf) {
        int tap = s >> 2, kc = s & 3;
        int ki = tap / 5, kj = tap - ki * 5;
        uint32_t base = sb + buf * BUFSZ;
        if (path == 0 || tid < 128) {
            const char* arow =
                (const char*)(aplane + ((size_t)((py + ki) * W_ + (px + kj))) * 128)
                + kc * 64;
            uint32_t adst = base + a_sm_base;
            #pragma unroll
            for (int j = 0; j < 4; ++j)
                cp16(adst + (uint32_t)((j ^ aq) << 4), arow + j * 16);
        }
        const char* bsrc = wblk + (size_t)tap * 2 * 32768
                         + (size_t)br * 256 + kc * 64 + (tid & 1) * 32;
        uint32_t bdst = base + b_sm_base;
        #pragma unroll
        for (int jj = 0; jj < 2; ++jj) {
            int j = 2 * (tid & 1) + jj;
            uint32_t so = (uint32_t)((j ^ bq) << 4);
            cp16(bdst + so, bsrc + jj * 16);
            if (path == 0)
                cp16(bdst + (OFF_BL - OFF_BH) + so, bsrc + 32768 + jj * 16);
        }
        cp_commit();
    };

    // ---- ldmatrix swizzled offsets (ks=0; ks=1 toggles bit 5) ----
    int rA = warp_m * 64 + (lane & 15);
    int cA = lane >> 4;
    uint32_t offA[4];
    #pragma unroll
    for (int mi = 0; mi < 4; ++mi) {
        int row = rA + mi * 16;
        offA[mi] = (uint32_t)((row >> 1) * 128 + (row & 1) * 64
                   + ((cA ^ ((row >> 1) & 3)) << 4));
    }
    int rB = warp_n * 32 + ((lane >> 4) << 3) + (lane & 7);
    int cB = (lane >> 3) & 1;
    uint32_t offB[2];
    #pragma unroll
    for (int n2 = 0; n2 < 2; ++n2) {
        int row = rB + n2 * 16;
        offB[n2] = (uint32_t)((row >> 1) * 128 + (row & 1) * 64
                   + ((cB ^ ((row >> 1) & 3)) << 4));
    }

    // per-warp k-slice phase skew
    uint32_t kskew = (uint32_t)(wid & 1) * 32u;

    float acc[4][4][4];
    #pragma unroll
    for (int mi = 0; mi < 4; ++mi)
        #pragma unroll
        for (int ni = 0; ni < 4; ++ni)
            #pragma unroll
            for (int j = 0; j < 4; ++j) acc[mi][ni][j] = 0.0f;

    stage(0, 0);
    stage(1, 1);

    for (int s = 0; s < NSTAGE; ++s) {
        int buf = s % 3;
        // 1) guarantee my stage(s) copies landed (leave s+1 in flight)
        if (s + 1 < NSTAGE) cp_wait<1>(); else cp_wait<0>();
        // 2) publish everyone's stage(s) data; also confirms buffer (s-1)%3
        //    (== (s+2)%3) has been fully consumed by all threads
        __syncthreads();
        // 3) refill the freed buffer
        if (s + 2 < NSTAGE) stage(s + 2, (s + 2) % 3);

        uint32_t base = sb + buf * BUFSZ;

        #pragma unroll
        for (int ksi = 0; ksi < 2; ++ksi) {
            uint32_t x = ((uint32_t)ksi * 32u) ^ kskew;   // de-phased slice order
            uint32_t ah[4][4], bh[2][4];
            #pragma unroll
            for (int mi = 0; mi < 4; ++mi)
                ldsm4(ah[mi], base + (offA[mi] ^ x));
            #pragma unroll
            for (int n2 = 0; n2 < 2; ++n2)
                ldsm4(bh[n2], base + OFF_BH + (offB[n2] ^ x));

            // term 1: ah * bh  (16 independent MMAs)
            #pragma unroll
            for (int mi = 0; mi < 4; ++mi)
                #pragma unroll
                for (int n2 = 0; n2 < 2; ++n2) {
                    MMA(acc[mi][2*n2],   ah[mi], bh[n2][0], bh[n2][1]);
                    MMA(acc[mi][2*n2+1], ah[mi], bh[n2][2], bh[n2][3]);
                }

            if (path == 0) {
                uint32_t al[4][4];
                #pragma unroll
                for (int mi = 0; mi < 4; ++mi)
                    ldsm4(al[mi], base + OFF_AL + (offA[mi] ^ x));
                // term 2: al * bh
                #pragma unroll
                for (int mi = 0; mi < 4; ++mi)
                    #pragma unroll
                    for (int n2 = 0; n2 < 2; ++n2) {
                        MMA(acc[mi][2*n2],   al[mi], bh[n2][0], bh[n2][1]);
                        MMA(acc[mi][2*n2+1], al[mi], bh[n2][2], bh[n2][3]);
                    }
                uint32_t bl[2][4];
                #pragma unroll
                for (int n2 = 0; n2 < 2; ++n2)
                    ldsm4(bl[n2], base + OFF_BL + (offB[n2] ^ x));
                // term 3: ah * bl
                #pragma unroll
                for (int mi = 0; mi < 4; ++mi)
                    #pragma unroll
                    for (int n2 = 0; n2 < 2; ++n2) {
                        MMA(acc[mi][2*n2],   ah[mi], bl[n2][0], bl[n2][1]);
                        MMA(acc[mi][2*n2+1], ah[mi], bl[n2][2], bl[n2][3]);
                    }
            }
        }
    }
    __syncthreads();

    // ---- epilogue: transpose via SMEM, coalesced float4 stores ----
    float* eps = (float*)smem;                 // [n=128][m pitch 132]
    #pragma unroll
    for (int mi = 0; mi < 4; ++mi) {
        int m0 = warp_m * 64 + mi * 16 + (lane >> 2);
        #pragma unroll
        for (int ni = 0; ni < 4; ++ni) {
            int n0 = warp_n * 32 + ni * 8 + 2 * (lane & 3);
            eps[n0 * 132 + m0]           = acc[mi][ni][0];
            eps[(n0 + 1) * 132 + m0]     = acc[mi][ni][1];
            eps[n0 * 132 + m0 + 8]       = acc[mi][ni][2];
            eps[(n0 + 1) * 132 + m0 + 8] = acc[mi][ni][3];
        }
    }
    __syncthreads();

    int pix0 = ptile * 128;
    int m = lane * 4;
    bool ok = (pix0 + m) < HW_OUT;
    if (path == 0) {
        #pragma unroll 1
        for (int rr = 0; rr < 16; ++rr) {
            int r = rr * 8 + wid;
            int o = og * 128 + r;
            float4 v = *(float4*)&eps[r * 132 + m];
            float bz = bias[o];
            v.x += bz; v.y += bz; v.z += bz; v.w += bz;
            if (ok)
                *(float4*)&out[((size_t)(b * O_ + o)) * HW_OUT + pix0 + m] = v;
        }
    } else {
        float* out2 = out + (size_t)B_ * O_ * HW_OUT;
        float4 sv = make_float4(0.f, 0.f, 0.f, 0.f);
        if (ok) sv = *(float4*)&g_S[(size_t)b * HW_OUT + pix0 + m];
        #pragma unroll 1
        for (int rr = 0; rr < 16; ++rr) {
            int r = rr * 8 + wid;
            int o = og * 128 + r;
            float4 v = *(float4*)&eps[r * 132 + m];
            float sp = g_sp[o];
            v.x = (sp * sv.x + v.x) * 0.001f;
            v.y = (sp * sv.y + v.y) * 0.001f;
            v.z = (sp * sv.z + v.z) * 0.001f;
            v.w = (sp * sv.w + v.w) * 0.001f;
            if (ok)
                *(float4*)&out2[((size_t)(b * O_ + o)) * HW_OUT + pix0 + m] = v;
        }
    }
}

// ---------------------------------------------------------------------------
extern "C" void kernel_launch(void* const* d_in, const int* in_sizes, int n_in,
                              void* d_out, int out_size) {
    const float* mu_x    = (const float*)d_in[0];
    const float* sigma_x = (const float*)d_in[1];
    const float* W       = (const float*)d_in[2];
    const float* bias    = (const float*)d_in[3];
    const float* w_sigma = (const float*)d_in[4];
    float* out = (float*)d_out;

    cudaFuncSetAttribute(mma_conv_kernel,
                         cudaFuncAttributeMaxDynamicSharedMemorySize, SMEM_MAIN);

    {
        dim3 g(HW_IN / 64, B_, 2);                 // 144 x 16 x 2
        transpose_split_kernel<<<g, 256>>>(mu_x, sigma_x);
    }
    wprep_kernel<<<(O_ * C_ + 255) / 256, 256>>>(W, w_sigma);
    {
        int n = B_ * HW_OUT;
        boxsum_kernel<<<(n + 255) / 256, 256>>>();
    }
    {
        dim3 grid(NPT, B_, 4);                     // 67 x 16 x 4 = 4288 CTAs
        mma_conv_kernel<<<grid, 256, SMEM_MAIN>>>(bias, out);
    }
}

// round 12
// speedup vs baseline: 1.1745x; 1.1745x over previous
#include <cuda_runtime.h>
#include <cuda_bf16.h>
#include <cuda_fp16.h>
#include <math.h>
#include <stdint.h>

#define B_  16
#define C_  128
#define O_  256
#define H_  96
#define W_  96
#define KH  5
#define HO  92
#define WO  92
#define HW_IN  (H_*W_)        // 9216
#define HW_OUT (HO*WO)        // 8464
#define KK  25
#define NPT 67                // ceil(8464/128)
#define NSTAGE 100            // 25 taps * 4 k32-chunks

// ---------------- device scratch (no allocation allowed) ----------------
// 16-bit planes: path0 = fp16 hi of mu, path1 = bf16 of sigma; g_Al = fp16 lo of mu
__device__ __align__(128) unsigned short g_Ah[(size_t)2*B_*HW_IN*128];
__device__ __align__(128) unsigned short g_Al[(size_t)B_*HW_IN*128];
// Weights: [path][og][tap][o_local(128)][c(128)]: path0 = fp16 W, path1 = bf16 W^2
__device__ __align__(128) unsigned short g_Wp[(size_t)2*2*KK*16384];
__device__ float g_Tp[2*B_*HW_IN];   // [path][b][pix]: path0 = sum mu^2, path1 = sum sigma
__device__ float g_S [B_*HW_OUT];
__device__ float g_sp[O_];

// ---------------- PTX helpers ----------------
__device__ __forceinline__ uint32_t smem_u32(const void* p){
    return (uint32_t)__cvta_generic_to_shared((void*)p);
}
__device__ __forceinline__ void cp16(uint32_t dst, const void* src){
    asm volatile("cp.async.cg.shared.global [%0], [%1], 16;\n" :: "r"(dst), "l"(src));
}
__device__ __forceinline__ void cp_commit(){ asm volatile("cp.async.commit_group;\n" ::: "memory"); }
template<int N> __device__ __forceinline__ void cp_wait(){
    asm volatile("cp.async.wait_group %0;\n" :: "n"(N) : "memory");
}
__device__ __forceinline__ void ldsm4(uint32_t* r, uint32_t addr){
    asm volatile("ldmatrix.sync.aligned.m8n8.x4.shared.b16 {%0,%1,%2,%3}, [%4];"
        : "=r"(r[0]), "=r"(r[1]), "=r"(r[2]), "=r"(r[3]) : "r"(addr));
}
// bf16 MMA (sigma path)
#define MMAB(acc, a, b0, b1)                                                       \
    asm volatile("mma.sync.aligned.m16n8k16.row.col.f32.bf16.bf16.f32 "            \
                 "{%0,%1,%2,%3},{%4,%5,%6,%7},{%8,%9},{%0,%1,%2,%3};"              \
                 : "+f"((acc)[0]), "+f"((acc)[1]), "+f"((acc)[2]), "+f"((acc)[3])  \
                 : "r"((a)[0]), "r"((a)[1]), "r"((a)[2]), "r"((a)[3]),             \
                   "r"(b0), "r"(b1))
// fp16 MMA (mu path)
#define MMAH(acc, a, b0, b1)                                                       \
    asm volatile("mma.sync.aligned.m16n8k16.row.col.f32.f16.f16.f32 "              \
                 "{%0,%1,%2,%3},{%4,%5,%6,%7},{%8,%9},{%0,%1,%2,%3};"              \
                 : "+f"((acc)[0]), "+f"((acc)[1]), "+f"((acc)[2]), "+f"((acc)[3])  \
                 : "r"((a)[0]), "r"((a)[1]), "r"((a)[2]), "r"((a)[3]),             \
                   "r"(b0), "r"(b1))

// ---------------- prep kernels ----------------
__global__ void transpose_split_kernel(const float* __restrict__ mu,
                                       const float* __restrict__ sg) {
    __shared__ float ts[C_][65];
    int pt = blockIdx.x, b = blockIdx.y, path = blockIdx.z;
    const float* src = (path ? sg : mu) + (size_t)b * C_ * HW_IN + pt * 64;
    int tid = threadIdx.x;
    for (int i = tid; i < C_ * 64; i += 256) {
        int c = i >> 6, pi = i & 63;
        ts[c][pi] = src[(size_t)c * HW_IN + pi];
    }
    __syncthreads();
    size_t obase = (size_t)(path * B_ + b) * HW_IN * 128;
    int p0 = pt * 64;
    for (int i = tid; i < 64 * C_; i += 256) {
        int pi = i >> 7, c = i & 127;
        float v = ts[c][pi];
        size_t idx = obase + (size_t)(p0 + pi) * 128 + c;
        if (path == 0) {
            __half hi = __float2half(v);
            g_Ah[idx] = __half_as_ushort(hi);
            g_Al[(size_t)b * HW_IN * 128 + (size_t)(p0 + pi) * 128 + c] =
                __half_as_ushort(__float2half(v - __half2float(hi)));
        } else {
            g_Ah[idx] = __bfloat16_as_ushort(__float2bfloat16(v));
        }
    }
    // fused channel sum: path0 -> sum mu^2, path1 -> sum sigma
    if (tid < 64) {
        float acc = 0.0f;
        #pragma unroll 8
        for (int c = 0; c < C_; ++c) {
            float v = ts[c][tid];
            acc += path ? v : v * v;
        }
        g_Tp[(size_t)(path * B_ + b) * HW_IN + p0 + tid] = acc;
    }
}

__global__ void wprep_kernel(const float* __restrict__ W,
                             const float* __restrict__ w_sigma) {
    int gid = blockIdx.x * blockDim.x + threadIdx.x;
    if (gid < O_) {
        float w = fmaxf(w_sigma[gid], -88.0f);
        g_sp[gid] = log1pf(expf(w));
    }
    if (gid >= O_ * C_) return;
    int o = gid >> 7, c = gid & 127;
    int og = o >> 7, ol = o & 127;
    const float* wp = W + ((size_t)o * C_ + c) * KK;
    int dst_in = ol * 128 + c;
    #pragma unroll
    for (int tap = 0; tap < KK; ++tap) {
        float w  = wp[tap];
        size_t blk0 = (size_t)((0 * 2 + og) * KK + tap);
        size_t blk1 = (size_t)((1 * 2 + og) * KK + tap);
        g_Wp[blk0 * 16384 + dst_in] = __half_as_ushort(__float2half(w));
        g_Wp[blk1 * 16384 + dst_in] = __bfloat16_as_ushort(__float2bfloat16(w * w));
    }
}

__global__ void boxsum_kernel() {
    int i = blockIdx.x * blockDim.x + threadIdx.x;
    if (i >= B_*HW_OUT) return;
    int b = i / HW_OUT;
    int p = i - b * HW_OUT;
    int y = p / WO;
    int x = p - y * WO;
    const float* t0 = g_Tp + (size_t)b * HW_IN;
    const float* t1 = g_Tp + (size_t)(B_ + b) * HW_IN;
    float acc = 0.0f;
    #pragma unroll
    for (int dy = 0; dy < KH; ++dy)
        #pragma unroll
        for (int dx = 0; dx < KH; ++dx) {
            int off = (y + dy) * W_ + (x + dx);
            acc += t0[off] + t1[off];
        }
    g_S[i] = acc;
}

// ---------------- main mma.sync conv: k32 stages, ring-3, 2 CTA/SM ----------------
// Buffer (32KB slot, 24KB used): Ah 8K | Al 8K | Bh 8K. Ring of 3 = 96KB.
// path0 (mu): fp16, 2 terms (ah*bh + al*bh).  path1 (sigma): bf16, 1 term.
// 64B k32 rows packed in pairs per 128B line, swizzle: (row>>1)*128 + (row&1)*64
//   + ((chunk ^ ((row>>1)&3))<<4)  -> conflict-free ldmatrix phases.
#define BUFSZ   32768u
#define OFF_AL  8192u
#define OFF_BH  16384u
#define SMEM_MAIN 98304

__global__ void __launch_bounds__(256, 2)
mma_conv_kernel(const float* __restrict__ bias, float* __restrict__ out) {
    extern __shared__ char smem[];
    uint32_t sb = smem_u32(smem);
    int tid = threadIdx.x;
    int lane = tid & 31, wid = tid >> 5;
    int warp_m = wid >> 2, warp_n = wid & 3;

    int ptile = blockIdx.x, b = blockIdx.y;
    int path = blockIdx.z & 1, og = blockIdx.z >> 1;

    // ---- staging setup ----
    int m_pix = tid & 127;
    int p  = ptile * 128 + m_pix;
    int pc = min(p, HW_OUT - 1);
    int py = pc / WO, px = pc - py * WO;
    const unsigned short* aplane =
        (tid < 128 ? g_Ah + (size_t)(path * B_ + b) * HW_IN * 128
                   : g_Al + (size_t)b * HW_IN * 128);
    uint32_t a_sm_base = (tid < 128 ? 0u : OFF_AL)
                       + (uint32_t)((m_pix >> 1) * 128 + (m_pix & 1) * 64);
    int aq = (m_pix >> 1) & 3;

    int br = tid >> 1;                       // weight row 0..127
    const char* wblk = (const char*)g_Wp +
        (size_t)((path * 2 + og) * KK) * 32768;
    uint32_t b_sm_base = OFF_BH + (uint32_t)((br >> 1) * 128 + (br & 1) * 64);
    int bq = (br >> 1) & 3;

    auto stage = [&](int s, int buf) {
        int tap = s >> 2, kc = s & 3;
        int ki = tap / 5, kj = tap - ki * 5;
        uint32_t base = sb + buf * BUFSZ;
        if (path == 0 || tid < 128) {
            const char* arow =
                (const char*)(aplane + ((size_t)((py + ki) * W_ + (px + kj))) * 128)
                + kc * 64;
            uint32_t adst = base + a_sm_base;
            #pragma unroll
            for (int j = 0; j < 4; ++j)
                cp16(adst + (uint32_t)((j ^ aq) << 4), arow + j * 16);
        }
        const char* bsrc = wblk + (size_t)tap * 32768
                         + (size_t)br * 256 + kc * 64 + (tid & 1) * 32;
        uint32_t bdst = base + b_sm_base;
        #pragma unroll
        for (int jj = 0; jj < 2; ++jj) {
            int j = 2 * (tid & 1) + jj;
            uint32_t so = (uint32_t)((j ^ bq) << 4);
            cp16(bdst + so, bsrc + jj * 16);
        }
        cp_commit();
    };

    // ---- ldmatrix swizzled offsets (ks=0; ks=1 toggles bit 5) ----
    int rA = warp_m * 64 + (lane & 15);
    int cA = lane >> 4;
    uint32_t offA[4];
    #pragma unroll
    for (int mi = 0; mi < 4; ++mi) {
        int row = rA + mi * 16;
        offA[mi] = (uint32_t)((row >> 1) * 128 + (row & 1) * 64
                   + ((cA ^ ((row >> 1) & 3)) << 4));
    }
    int rB = warp_n * 32 + ((lane >> 4) << 3) + (lane & 7);
    int cB = (lane >> 3) & 1;
    uint32_t offB[2];
    #pragma unroll
    for (int n2 = 0; n2 < 2; ++n2) {
        int row = rB + n2 * 16;
        offB[n2] = (uint32_t)((row >> 1) * 128 + (row & 1) * 64
                   + ((cB ^ ((row >> 1) & 3)) << 4));
    }

    float acc[4][4][4];
    #pragma unroll
    for (int mi = 0; mi < 4; ++mi)
        #pragma unroll
        for (int ni = 0; ni < 4; ++ni)
            #pragma unroll
            for (int j = 0; j < 4; ++j) acc[mi][ni][j] = 0.0f;

    stage(0, 0);
    stage(1, 1);

    for (int s = 0; s < NSTAGE; ++s) {
        int buf = s % 3;
        // 1) guarantee my stage(s) copies landed (leave s+1 in flight)
        if (s + 1 < NSTAGE) cp_wait<1>(); else cp_wait<0>();
        // 2) publish everyone's stage(s) data; also confirms buffer (s-1)%3
        //    (== (s+2)%3) has been fully consumed by all threads
        __syncthreads();
        // 3) refill the freed buffer
        if (s + 2 < NSTAGE) stage(s + 2, (s + 2) % 3);

        uint32_t base = sb + buf * BUFSZ;

        #pragma unroll
        for (int ks = 0; ks < 2; ++ks) {
            uint32_t x = ks ? 32u : 0u;
            uint32_t ah[4][4], bh[2][4];
            #pragma unroll
            for (int mi = 0; mi < 4; ++mi)
                ldsm4(ah[mi], base + (offA[mi] ^ x));
            #pragma unroll
            for (int n2 = 0; n2 < 2; ++n2)
                ldsm4(bh[n2], base + OFF_BH + (offB[n2] ^ x));

            if (path == 0) {
                // term 1: ah * bh (fp16)
                #pragma unroll
                for (int mi = 0; mi < 4; ++mi)
                    #pragma unroll
                    for (int n2 = 0; n2 < 2; ++n2) {
                        MMAH(acc[mi][2*n2],   ah[mi], bh[n2][0], bh[n2][1]);
                        MMAH(acc[mi][2*n2+1], ah[mi], bh[n2][2], bh[n2][3]);
                    }
                uint32_t al[4][4];
                #pragma unroll
                for (int mi = 0; mi < 4; ++mi)
                    ldsm4(al[mi], base + OFF_AL + (offA[mi] ^ x));
                // term 2: al * bh (fp16)
                #pragma unroll
                for (int mi = 0; mi < 4; ++mi)
                    #pragma unroll
                    for (int n2 = 0; n2 < 2; ++n2) {
                        MMAH(acc[mi][2*n2],   al[mi], bh[n2][0], bh[n2][1]);
                        MMAH(acc[mi][2*n2+1], al[mi], bh[n2][2], bh[n2][3]);
                    }
            } else {
                // single term: ah * bh (bf16)
                #pragma unroll
                for (int mi = 0; mi < 4; ++mi)
                    #pragma unroll
                    for (int n2 = 0; n2 < 2; ++n2) {
                        MMAB(acc[mi][2*n2],   ah[mi], bh[n2][0], bh[n2][1]);
                        MMAB(acc[mi][2*n2+1], ah[mi], bh[n2][2], bh[n2][3]);
                    }
            }
        }
    }
    __syncthreads();

    // ---- epilogue: transpose via SMEM, coalesced float4 stores ----
    float* eps = (float*)smem;                 // [n=128][m pitch 132]
    #pragma unroll
    for (int mi = 0; mi < 4; ++mi) {
        int m0 = warp_m * 64 + mi * 16 + (lane >> 2);
        #pragma unroll
        for (int ni = 0; ni < 4; ++ni) {
            int n0 = warp_n * 32 + ni * 8 + 2 * (lane & 3);
            eps[n0 * 132 + m0]           = acc[mi][ni][0];
            eps[(n0 + 1) * 132 + m0]     = acc[mi][ni][1];
            eps[n0 * 132 + m0 + 8]       = acc[mi][ni][2];
            eps[(n0 + 1) * 132 + m0 + 8] = acc[mi][ni][3];
        }
    }
    __syncthreads();

    int pix0 = ptile * 128;
    int m = lane * 4;
    bool ok = (pix0 + m) < HW_OUT;
    if (path == 0) {
        #pragma unroll 1
        for (int rr = 0; rr < 16; ++rr) {
            int r = rr * 8 + wid;
            int o = og * 128 + r;
            float4 v = *(float4*)&eps[r * 132 + m];
            float bz = bias[o];
            v.x += bz; v.y += bz; v.z += bz; v.w += bz;
            if (ok)
                *(float4*)&out[((size_t)(b * O_ + o)) * HW_OUT + pix0 + m] = v;
        }
    } else {
        float* out2 = out + (size_t)B_ * O_ * HW_OUT;
        float4 sv = make_float4(0.f, 0.f, 0.f, 0.f);
        if (ok) sv = *(float4*)&g_S[(size_t)b * HW_OUT + pix0 + m];
        #pragma unroll 1
        for (int rr = 0; rr < 16; ++rr) {
            int r = rr * 8 + wid;
            int o = og * 128 + r;
            float4 v = *(float4*)&eps[r * 132 + m];
            float sp = g_sp[o];
            v.x = (sp * sv.x + v.x) * 0.001f;
            v.y = (sp * sv.y + v.y) * 0.001f;
            v.z = (sp * sv.z + v.z) * 0.001f;
            v.w = (sp * sv.w + v.w) * 0.001f;
            if (ok)
                *(float4*)&out2[((size_t)(b * O_ + o)) * HW_OUT + pix0 + m] = v;
        }
    }
}

// ---------------------------------------------------------------------------
extern "C" void kernel_launch(void* const* d_in, const int* in_sizes, int n_in,
                              void* d_out, int out_size) {
    const float* mu_x    = (const float*)d_in[0];
    const float* sigma_x = (const float*)d_in[1];
    const float* W       = (const float*)d_in[2];
    const float* bias    = (const float*)d_in[3];
    const float* w_sigma = (const float*)d_in[4];
    float* out = (float*)d_out;

    cudaFuncSetAttribute(mma_conv_kernel,
                         cudaFuncAttributeMaxDynamicSharedMemorySize, SMEM_MAIN);

    {
        dim3 g(HW_IN / 64, B_, 2);                 // 144 x 16 x 2
        transpose_split_kernel<<<g, 256>>>(mu_x, sigma_x);
    }
    wprep_kernel<<<(O_ * C_ + 255) / 256, 256>>>(W, w_sigma);
    {
        int n = B_ * HW_OUT;
        boxsum_kernel<<<(n + 255) / 256, 256>>>();
    }
    {
        dim3 grid(NPT, B_, 4);                     // 67 x 16 x 4 = 4288 CTAs
        mma_conv_kernel<<<grid, 256, SMEM_MAIN>>>(bias, out);
    }
}

// round 13
// speedup vs baseline: 1.8127x; 1.5433x over previous
#include <cuda_runtime.h>
#include <cuda_bf16.h>
#include <cuda_fp16.h>
#include <math.h>
#include <stdint.h>

#define B_  16
#define C_  128
#define O_  256
#define H_  96
#define W_  96
#define KH  5
#define HO  92
#define WO  92
#define HW_IN  (H_*W_)        // 9216
#define HW_OUT (HO*WO)        // 8464
#define KK  25
#define NPT 67                // ceil(8464/128)
#define NSTAGE 100            // 25 taps * 4 k32-chunks

// ---------------- device scratch (no allocation allowed) ----------------
// 16-bit planes: path0 = fp16 mu, path1 = bf16 sigma  [path][b][pix][c]
__device__ __align__(128) unsigned short g_Ah[(size_t)2*B_*HW_IN*128];
// Weights: [path][og][tap][o_local(128)][c(128)]: path0 = fp16 W, path1 = bf16 W^2
__device__ __align__(128) unsigned short g_Wp[(size_t)2*2*KK*16384];
__device__ float g_Tp[2*B_*HW_IN];   // [path][b][pix]: path0 = sum mu^2, path1 = sum sigma
__device__ float g_S [B_*HW_OUT];
__device__ float g_sp[O_];

// ---------------- PTX helpers ----------------
__device__ __forceinline__ uint32_t smem_u32(const void* p){
    return (uint32_t)__cvta_generic_to_shared((void*)p);
}
__device__ __forceinline__ void cp16(uint32_t dst, const void* src){
    asm volatile("cp.async.cg.shared.global [%0], [%1], 16;\n" :: "r"(dst), "l"(src));
}
__device__ __forceinline__ void cp_commit(){ asm volatile("cp.async.commit_group;\n" ::: "memory"); }
template<int N> __device__ __forceinline__ void cp_wait(){
    asm volatile("cp.async.wait_group %0;\n" :: "n"(N) : "memory");
}
__device__ __forceinline__ void ldsm4(uint32_t* r, uint32_t addr){
    asm volatile("ldmatrix.sync.aligned.m8n8.x4.shared.b16 {%0,%1,%2,%3}, [%4];"
        : "=r"(r[0]), "=r"(r[1]), "=r"(r[2]), "=r"(r[3]) : "r"(addr));
}
// bf16 MMA (sigma path)
#define MMAB(acc, a, b0, b1)                                                       \
    asm volatile("mma.sync.aligned.m16n8k16.row.col.f32.bf16.bf16.f32 "            \
                 "{%0,%1,%2,%3},{%4,%5,%6,%7},{%8,%9},{%0,%1,%2,%3};"              \
                 : "+f"((acc)[0]), "+f"((acc)[1]), "+f"((acc)[2]), "+f"((acc)[3])  \
                 : "r"((a)[0]), "r"((a)[1]), "r"((a)[2]), "r"((a)[3]),             \
                   "r"(b0), "r"(b1))
// fp16 MMA (mu path)
#define MMAH(acc, a, b0, b1)                                                       \
    asm volatile("mma.sync.aligned.m16n8k16.row.col.f32.f16.f16.f32 "              \
                 "{%0,%1,%2,%3},{%4,%5,%6,%7},{%8,%9},{%0,%1,%2,%3};"              \
                 : "+f"((acc)[0]), "+f"((acc)[1]), "+f"((acc)[2]), "+f"((acc)[3])  \
                 : "r"((a)[0]), "r"((a)[1]), "r"((a)[2]), "r"((a)[3]),             \
                   "r"(b0), "r"(b1))

// ---------------- prep kernels ----------------
__global__ void transpose_split_kernel(const float* __restrict__ mu,
                                       const float* __restrict__ sg) {
    __shared__ float ts[C_][65];
    int pt = blockIdx.x, b = blockIdx.y, path = blockIdx.z;
    const float* src = (path ? sg : mu) + (size_t)b * C_ * HW_IN + pt * 64;
    int tid = threadIdx.x;
    for (int i = tid; i < C_ * 64; i += 256) {
        int c = i >> 6, pi = i & 63;
        ts[c][pi] = src[(size_t)c * HW_IN + pi];
    }
    __syncthreads();
    size_t obase = (size_t)(path * B_ + b) * HW_IN * 128;
    int p0 = pt * 64;
    for (int i = tid; i < 64 * C_; i += 256) {
        int pi = i >> 7, c = i & 127;
        float v = ts[c][pi];
        size_t idx = obase + (size_t)(p0 + pi) * 128 + c;
        g_Ah[idx] = path == 0 ? __half_as_ushort(__float2half(v))
                              : __bfloat16_as_ushort(__float2bfloat16(v));
    }
    // fused channel sum: path0 -> sum mu^2, path1 -> sum sigma
    if (tid < 64) {
        float acc = 0.0f;
        #pragma unroll 8
        for (int c = 0; c < C_; ++c) {
            float v = ts[c][tid];
            acc += path ? v : v * v;
        }
        g_Tp[(size_t)(path * B_ + b) * HW_IN + p0 + tid] = acc;
    }
}

__global__ void wprep_kernel(const float* __restrict__ W,
                             const float* __restrict__ w_sigma) {
    int gid = blockIdx.x * blockDim.x + threadIdx.x;
    if (gid < O_) {
        float w = fmaxf(w_sigma[gid], -88.0f);
        g_sp[gid] = log1pf(expf(w));
    }
    if (gid >= O_ * C_) return;
    int o = gid >> 7, c = gid & 127;
    int og = o >> 7, ol = o & 127;
    const float* wp = W + ((size_t)o * C_ + c) * KK;
    int dst_in = ol * 128 + c;
    #pragma unroll
    for (int tap = 0; tap < KK; ++tap) {
        float w  = wp[tap];
        size_t blk0 = (size_t)((0 * 2 + og) * KK + tap);
        size_t blk1 = (size_t)((1 * 2 + og) * KK + tap);
        g_Wp[blk0 * 16384 + dst_in] = __half_as_ushort(__float2half(w));
        g_Wp[blk1 * 16384 + dst_in] = __bfloat16_as_ushort(__float2bfloat16(w * w));
    }
}

__global__ void boxsum_kernel() {
    int i = blockIdx.x * blockDim.x + threadIdx.x;
    if (i >= B_*HW_OUT) return;
    int b = i / HW_OUT;
    int p = i - b * HW_OUT;
    int y = p / WO;
    int x = p - y * WO;
    const float* t0 = g_Tp + (size_t)b * HW_IN;
    const float* t1 = g_Tp + (size_t)(B_ + b) * HW_IN;
    float acc = 0.0f;
    #pragma unroll
    for (int dy = 0; dy < KH; ++dy)
        #pragma unroll
        for (int dx = 0; dx < KH; ++dx) {
            int off = (y + dy) * W_ + (x + dx);
            acc += t0[off] + t1[off];
        }
    g_S[i] = acc;
}

// ---------------- main mma.sync conv: k32 stages, ring-4, 2 CTA/SM ----------------
// Buffer (16KB): A 8K | B 8K. Ring of 4 = 64KB. Both paths single-term:
// path0 (mu): fp16 a*b. path1 (sigma): bf16 a*b.
// 64B k32 rows packed in pairs per 128B line, swizzle: (row>>1)*128 + (row&1)*64
//   + ((chunk ^ ((row>>1)&3))<<4)  -> conflict-free ldmatrix phases.
#define BUFSZ   16384u
#define OFF_BH  8192u
#define SMEM_MAIN 69632   // epilogue needs 128*132*4 = 67584

__global__ void __launch_bounds__(256, 2)
mma_conv_kernel(const float* __restrict__ bias, float* __restrict__ out) {
    extern __shared__ char smem[];
    uint32_t sb = smem_u32(smem);
    int tid = threadIdx.x;
    int lane = tid & 31, wid = tid >> 5;
    int warp_m = wid >> 2, warp_n = wid & 3;

    int ptile = blockIdx.x, b = blockIdx.y;
    int path = blockIdx.z & 1, og = blockIdx.z >> 1;

    // ---- staging setup: A spread over all 256 threads (row = tid>>1, half = tid&1)
    int ar  = tid >> 1;                      // pixel row 0..127
    int ah2 = tid & 1;                       // which 32B half of the 64B chunk
    int pA  = ptile * 128 + ar;
    int pcA = min(pA, HW_OUT - 1);
    int py = pcA / WO, px = pcA - py * WO;
    const unsigned short* aplane = g_Ah + (size_t)(path * B_ + b) * HW_IN * 128;
    uint32_t a_sm_base = (uint32_t)((ar >> 1) * 128 + (ar & 1) * 64);
    int aq = (ar >> 1) & 3;

    int br = tid >> 1;                       // weight row 0..127
    const char* wblk = (const char*)g_Wp +
        (size_t)((path * 2 + og) * KK) * 32768;
    uint32_t b_sm_base = OFF_BH + (uint32_t)((br >> 1) * 128 + (br & 1) * 64);
    int bq = (br >> 1) & 3;

    auto stage = [&](int s, int buf) {
        int tap = s >> 2, kc = s & 3;
        int ki = tap / 5, kj = tap - ki * 5;
        uint32_t base = sb + buf * BUFSZ;
        // A: this thread's 32B of row ar's 64B k-chunk
        const char* arow =
            (const char*)(aplane + ((size_t)((py + ki) * W_ + (px + kj))) * 128)
            + kc * 64 + ah2 * 32;
        uint32_t adst = base + a_sm_base;
        #pragma unroll
        for (int jj = 0; jj < 2; ++jj) {
            int j = 2 * ah2 + jj;
            cp16(adst + (uint32_t)((j ^ aq) << 4), arow + jj * 16);
        }
        // B: this thread's 32B of weight row br's 64B k-chunk
        const char* bsrc = wblk + (size_t)tap * 32768
                         + (size_t)br * 256 + kc * 64 + ah2 * 32;
        uint32_t bdst = base + b_sm_base;
        #pragma unroll
        for (int jj = 0; jj < 2; ++jj) {
            int j = 2 * ah2 + jj;
            cp16(bdst + (uint32_t)((j ^ bq) << 4), bsrc + jj * 16);
        }
        cp_commit();
    };

    // ---- ldmatrix swizzled offsets (ks=0; ks=1 toggles bit 5) ----
    int rA = warp_m * 64 + (lane & 15);
    int cA = lane >> 4;
    uint32_t offA[4];
    #pragma unroll
    for (int mi = 0; mi < 4; ++mi) {
        int row = rA + mi * 16;
        offA[mi] = (uint32_t)((row >> 1) * 128 + (row & 1) * 64
                   + ((cA ^ ((row >> 1) & 3)) << 4));
    }
    int rB = warp_n * 32 + ((lane >> 4) << 3) + (lane & 7);
    int cB = (lane >> 3) & 1;
    uint32_t offB[2];
    #pragma unroll
    for (int n2 = 0; n2 < 2; ++n2) {
        int row = rB + n2 * 16;
        offB[n2] = (uint32_t)((row >> 1) * 128 + (row & 1) * 64
                   + ((cB ^ ((row >> 1) & 3)) << 4));
    }

    float acc[4][4][4];
    #pragma unroll
    for (int mi = 0; mi < 4; ++mi)
        #pragma unroll
        for (int ni = 0; ni < 4; ++ni)
            #pragma unroll
            for (int j = 0; j < 4; ++j) acc[mi][ni][j] = 0.0f;

    stage(0, 0);
    stage(1, 1);
    stage(2, 2);

    for (int s = 0; s < NSTAGE; ++s) {
        int buf = s & 3;
        // 1) ensure stage(s) landed (up to 2 younger stages stay in flight)
        if (s + 2 < NSTAGE)      cp_wait<2>();
        else if (s + 1 < NSTAGE) cp_wait<1>();
        else                     cp_wait<0>();
        // 2) publish stage(s); confirms buffer (s+3)&3 == (s-1)&3 fully consumed
        __syncthreads();
        // 3) refill the freed buffer, 3 stages ahead
        if (s + 3 < NSTAGE) stage(s + 3, (s + 3) & 3);

        uint32_t base = sb + buf * BUFSZ;

        #pragma unroll
        for (int ks = 0; ks < 2; ++ks) {
            uint32_t x = ks ? 32u : 0u;
            uint32_t ah[4][4], bh[2][4];
            #pragma unroll
            for (int mi = 0; mi < 4; ++mi)
                ldsm4(ah[mi], base + (offA[mi] ^ x));
            #pragma unroll
            for (int n2 = 0; n2 < 2; ++n2)
                ldsm4(bh[n2], base + OFF_BH + (offB[n2] ^ x));

            if (path == 0) {
                #pragma unroll
                for (int mi = 0; mi < 4; ++mi)
                    #pragma unroll
                    for (int n2 = 0; n2 < 2; ++n2) {
                        MMAH(acc[mi][2*n2],   ah[mi], bh[n2][0], bh[n2][1]);
                        MMAH(acc[mi][2*n2+1], ah[mi], bh[n2][2], bh[n2][3]);
                    }
            } else {
                #pragma unroll
                for (int mi = 0; mi < 4; ++mi)
                    #pragma unroll
                    for (int n2 = 0; n2 < 2; ++n2) {
                        MMAB(acc[mi][2*n2],   ah[mi], bh[n2][0], bh[n2][1]);
                        MMAB(acc[mi][2*n2+1], ah[mi], bh[n2][2], bh[n2][3]);
                    }
            }
        }
    }
    __syncthreads();

    // ---- epilogue: transpose via SMEM, coalesced float4 stores ----
    float* eps = (float*)smem;                 // [n=128][m pitch 132]
    #pragma unroll
    for (int mi = 0; mi < 4; ++mi) {
        int m0 = warp_m * 64 + mi * 16 + (lane >> 2);
        #pragma unroll
        for (int ni = 0; ni < 4; ++ni) {
            int n0 = warp_n * 32 + ni * 8 + 2 * (lane & 3);
            eps[n0 * 132 + m0]           = acc[mi][ni][0];
            eps[(n0 + 1) * 132 + m0]     = acc[mi][ni][1];
            eps[n0 * 132 + m0 + 8]       = acc[mi][ni][2];
            eps[(n0 + 1) * 132 + m0 + 8] = acc[mi][ni][3];
        }
    }
    __syncthreads();

    int pix0 = ptile * 128;
    int m = lane * 4;
    bool ok = (pix0 + m) < HW_OUT;
    if (path == 0) {
        #pragma unroll 1
        for (int rr = 0; rr < 16; ++rr) {
            int r = rr * 8 + wid;
            int o = og * 128 + r;
            float4 v = *(float4*)&eps[r * 132 + m];
            float bz = bias[o];
            v.x += bz; v.y += bz; v.z += bz; v.w += bz;
            if (ok)
                *(float4*)&out[((size_t)(b * O_ + o)) * HW_OUT + pix0 + m] = v;
        }
    } else {
        float* out2 = out + (size_t)B_ * O_ * HW_OUT;
        float4 sv = make_float4(0.f, 0.f, 0.f, 0.f);
        if (ok) sv = *(float4*)&g_S[(size_t)b * HW_OUT + pix0 + m];
        #pragma unroll 1
        for (int rr = 0; rr < 16; ++rr) {
            int r = rr * 8 + wid;
            int o = og * 128 + r;
            float4 v = *(float4*)&eps[r * 132 + m];
            float sp = g_sp[o];
            v.x = (sp * sv.x + v.x) * 0.001f;
            v.y = (sp * sv.y + v.y) * 0.001f;
            v.z = (sp * sv.z + v.z) * 0.001f;
            v.w = (sp * sv.w + v.w) * 0.001f;
            if (ok)
                *(float4*)&out2[((size_t)(b * O_ + o)) * HW_OUT + pix0 + m] = v;
        }
    }
}

// ---------------------------------------------------------------------------
extern "C" void kernel_launch(void* const* d_in, const int* in_sizes, int n_in,
                              void* d_out, int out_size) {
    const float* mu_x    = (const float*)d_in[0];
    const float* sigma_x = (const float*)d_in[1];
    const float* W       = (const float*)d_in[2];
    const float* bias    = (const float*)d_in[3];
    const float* w_sigma = (const float*)d_in[4];
    float* out = (float*)d_out;

    cudaFuncSetAttribute(mma_conv_kernel,
                         cudaFuncAttributeMaxDynamicSharedMemorySize, SMEM_MAIN);

    {
        dim3 g(HW_IN / 64, B_, 2);                 // 144 x 16 x 2
        transpose_split_kernel<<<g, 256>>>(mu_x, sigma_x);
    }
    wprep_kernel<<<(O_ * C_ + 255) / 256, 256>>>(W, w_sigma);
    {
        int n = B_ * HW_OUT;
        boxsum_kernel<<<(n + 255) / 256, 256>>>();
    }
    {
        dim3 grid(NPT, B_, 4);                     // 67 x 16 x 4 = 4288 CTAs
        mma_conv_kernel<<<grid, 256, SMEM_MAIN>>>(bias, out);
    }
}

// round 14
// speedup vs baseline: 1.9490x; 1.0752x over previous
#include <cuda_runtime.h>
#include <cuda_bf16.h>
#include <cuda_fp16.h>
#include <math.h>
#include <stdint.h>

#define B_  16
#define C_  128
#define O_  256
#define H_  96
#define W_  96
#define KH  5
#define HO  92
#define WO  92
#define HW_IN  (H_*W_)        // 9216
#define HW_OUT (HO*WO)        // 8464
#define KK  25
#define NPT 67                // ceil(8464/128)
#define NSTAGE 50             // 25 taps * 2 k64-chunks

// ---------------- device scratch (no allocation allowed) ----------------
// 16-bit planes: path0 = fp16 mu, path1 = bf16 sigma  [path][b][pix][c]
__device__ __align__(128) unsigned short g_Ah[(size_t)2*B_*HW_IN*128];
// Weights: [path][og][tap][o_local(128)][c(128)]: path0 = fp16 W, path1 = bf16 W^2
__device__ __align__(128) unsigned short g_Wp[(size_t)2*2*KK*16384];
__device__ float g_Tp[2*B_*HW_IN];   // [path][b][pix]: path0 = sum mu^2, path1 = sum sigma
__device__ float g_S [B_*HW_OUT];
__device__ float g_sp[O_];

// ---------------- PTX helpers ----------------
__device__ __forceinline__ uint32_t smem_u32(const void* p){
    return (uint32_t)__cvta_generic_to_shared((void*)p);
}
__device__ __forceinline__ void cp16(uint32_t dst, const void* src){
    asm volatile("cp.async.cg.shared.global [%0], [%1], 16;\n" :: "r"(dst), "l"(src));
}
__device__ __forceinline__ void cp_commit(){ asm volatile("cp.async.commit_group;\n" ::: "memory"); }
template<int N> __device__ __forceinline__ void cp_wait(){
    asm volatile("cp.async.wait_group %0;\n" :: "n"(N) : "memory");
}
__device__ __forceinline__ void ldsm4(uint32_t* r, uint32_t addr){
    asm volatile("ldmatrix.sync.aligned.m8n8.x4.shared.b16 {%0,%1,%2,%3}, [%4];"
        : "=r"(r[0]), "=r"(r[1]), "=r"(r[2]), "=r"(r[3]) : "r"(addr));
}
// bf16 MMA (sigma path)
#define MMAB(acc, a, b0, b1)                                                       \
    asm volatile("mma.sync.aligned.m16n8k16.row.col.f32.bf16.bf16.f32 "            \
                 "{%0,%1,%2,%3},{%4,%5,%6,%7},{%8,%9},{%0,%1,%2,%3};"              \
                 : "+f"((acc)[0]), "+f"((acc)[1]), "+f"((acc)[2]), "+f"((acc)[3])  \
                 : "r"((a)[0]), "r"((a)[1]), "r"((a)[2]), "r"((a)[3]),             \
                   "r"(b0), "r"(b1))
// fp16 MMA (mu path)
#define MMAH(acc, a, b0, b1)                                                       \
    asm volatile("mma.sync.aligned.m16n8k16.row.col.f32.f16.f16.f32 "              \
                 "{%0,%1,%2,%3},{%4,%5,%6,%7},{%8,%9},{%0,%1,%2,%3};"              \
                 : "+f"((acc)[0]), "+f"((acc)[1]), "+f"((acc)[2]), "+f"((acc)[3])  \
                 : "r"((a)[0]), "r"((a)[1]), "r"((a)[2]), "r"((a)[3]),             \
                   "r"(b0), "r"(b1))

// ---------------- prep kernels ----------------
__global__ void transpose_split_kernel(const float* __restrict__ mu,
                                       const float* __restrict__ sg) {
    __shared__ float ts[C_][65];
    int pt = blockIdx.x, b = blockIdx.y, path = blockIdx.z;
    const float* src = (path ? sg : mu) + (size_t)b * C_ * HW_IN + pt * 64;
    int tid = threadIdx.x;
    for (int i = tid; i < C_ * 64; i += 256) {
        int c = i >> 6, pi = i & 63;
        ts[c][pi] = src[(size_t)c * HW_IN + pi];
    }
    __syncthreads();
    size_t obase = (size_t)(path * B_ + b) * HW_IN * 128;
    int p0 = pt * 64;
    for (int i = tid; i < 64 * C_; i += 256) {
        int pi = i >> 7, c = i & 127;
        float v = ts[c][pi];
        size_t idx = obase + (size_t)(p0 + pi) * 128 + c;
        g_Ah[idx] = path == 0 ? __half_as_ushort(__float2half(v))
                              : __bfloat16_as_ushort(__float2bfloat16(v));
    }
    // fused channel sum: path0 -> sum mu^2, path1 -> sum sigma
    if (tid < 64) {
        float acc = 0.0f;
        #pragma unroll 8
        for (int c = 0; c < C_; ++c) {
            float v = ts[c][tid];
            acc += path ? v : v * v;
        }
        g_Tp[(size_t)(path * B_ + b) * HW_IN + p0 + tid] = acc;
    }
}

__global__ void wprep_kernel(const float* __restrict__ W,
                             const float* __restrict__ w_sigma) {
    int gid = blockIdx.x * blockDim.x + threadIdx.x;
    if (gid < O_) {
        float w = fmaxf(w_sigma[gid], -88.0f);
        g_sp[gid] = log1pf(expf(w));
    }
    if (gid >= O_ * C_) return;
    int o = gid >> 7, c = gid & 127;
    int og = o >> 7, ol = o & 127;
    const float* wp = W + ((size_t)o * C_ + c) * KK;
    int dst_in = ol * 128 + c;
    #pragma unroll
    for (int tap = 0; tap < KK; ++tap) {
        float w  = wp[tap];
        size_t blk0 = (size_t)((0 * 2 + og) * KK + tap);
        size_t blk1 = (size_t)((1 * 2 + og) * KK + tap);
        g_Wp[blk0 * 16384 + dst_in] = __half_as_ushort(__float2half(w));
        g_Wp[blk1 * 16384 + dst_in] = __bfloat16_as_ushort(__float2bfloat16(w * w));
    }
}

__global__ void boxsum_kernel() {
    int i = blockIdx.x * blockDim.x + threadIdx.x;
    if (i >= B_*HW_OUT) return;
    int b = i / HW_OUT;
    int p = i - b * HW_OUT;
    int y = p / WO;
    int x = p - y * WO;
    const float* t0 = g_Tp + (size_t)b * HW_IN;
    const float* t1 = g_Tp + (size_t)(B_ + b) * HW_IN;
    float acc = 0.0f;
    #pragma unroll
    for (int dy = 0; dy < KH; ++dy)
        #pragma unroll
        for (int dx = 0; dx < KH; ++dx) {
            int off = (y + dy) * W_ + (x + dx);
            acc += t0[off] + t1[off];
        }
    g_S[i] = acc;
}

// ---------------- main mma.sync conv: k64 stages, ring-3, 2 CTA/SM ----------------
// Buffer (32KB): A 16K | B 16K. Ring of 3 = 96KB. Both paths single-term.
// Each row (pixel / weight-o) = one 128B line (k64 = 64 halves). SW128 swizzle:
//   addr(row, chunk) = row*128 + ((chunk ^ (row&7)) << 4), chunk 0..7 (16B each).
// k16-slice ks (0..3) + col16 c (0,1): chunk = ks*2 + c -> addr = base ^ (ks<<5).
#define BUFSZ   32768u
#define OFF_BH  16384u
#define SMEM_MAIN 98304   // >= epilogue 128*132*4 = 67584

__global__ void __launch_bounds__(256, 2)
mma_conv_kernel(const float* __restrict__ bias, float* __restrict__ out) {
    extern __shared__ char smem[];
    uint32_t sb = smem_u32(smem);
    int tid = threadIdx.x;
    int lane = tid & 31, wid = tid >> 5;
    int warp_m = wid >> 2, warp_n = wid & 3;

    int ptile = blockIdx.x, b = blockIdx.y;
    int path = blockIdx.z & 1, og = blockIdx.z >> 1;

    // ---- staging setup: row = tid>>1 (0..127), half = tid&1 (64B each) ----
    int ar  = tid >> 1;
    int ah2 = tid & 1;
    int pA  = ptile * 128 + ar;
    int pcA = min(pA, HW_OUT - 1);
    int py = pcA / WO, px = pcA - py * WO;
    const unsigned short* aplane = g_Ah + (size_t)(path * B_ + b) * HW_IN * 128;
    uint32_t a_sm_base = (uint32_t)ar * 128;
    int aq = ar & 7;

    const char* wblk = (const char*)g_Wp +
        (size_t)((path * 2 + og) * KK) * 32768;

    auto stage = [&](int s, int buf) {
        int tap = s >> 1, kc = s & 1;
        int ki = tap / 5, kj = tap - ki * 5;
        uint32_t base = sb + buf * BUFSZ;
        // A: 64B half of this pixel-row's 128B k64 chunk
        const char* arow =
            (const char*)(aplane + ((size_t)((py + ki) * W_ + (px + kj))) * 128)
            + kc * 128 + ah2 * 64;
        uint32_t adst = base + a_sm_base;
        #pragma unroll
        for (int jj = 0; jj < 4; ++jj) {
            int j = 4 * ah2 + jj;
            cp16(adst + (uint32_t)((j ^ aq) << 4), arow + jj * 16);
        }
        // B: 64B half of weight row ar's 128B k64 chunk (same row index)
        const char* bsrc = wblk + (size_t)tap * 32768
                         + (size_t)ar * 256 + kc * 128 + ah2 * 64;
        uint32_t bdst = base + OFF_BH + a_sm_base;
        #pragma unroll
        for (int jj = 0; jj < 4; ++jj) {
            int j = 4 * ah2 + jj;
            cp16(bdst + (uint32_t)((j ^ aq) << 4), bsrc + jj * 16);
        }
        cp_commit();
    };

    // ---- ldmatrix swizzled base offsets (slice ks XORs addr with ks<<5) ----
    int rA = warp_m * 64 + (lane & 15);
    int cA = lane >> 4;
    uint32_t offA[4];
    #pragma unroll
    for (int mi = 0; mi < 4; ++mi) {
        int row = rA + mi * 16;
        offA[mi] = (uint32_t)(row * 128 + ((cA ^ (row & 7)) << 4));
    }
    int rB = warp_n * 32 + ((lane >> 4) << 3) + (lane & 7);
    int cB = (lane >> 3) & 1;
    uint32_t offB[2];
    #pragma unroll
    for (int n2 = 0; n2 < 2; ++n2) {
        int row = rB + n2 * 16;
        offB[n2] = (uint32_t)(row * 128 + ((cB ^ (row & 7)) << 4));
    }

    float acc[4][4][4];
    #pragma unroll
    for (int mi = 0; mi < 4; ++mi)
        #pragma unroll
        for (int ni = 0; ni < 4; ++ni)
            #pragma unroll
            for (int j = 0; j < 4; ++j) acc[mi][ni][j] = 0.0f;

    stage(0, 0);
    stage(1, 1);

    for (int s = 0; s < NSTAGE; ++s) {
        int buf = s % 3;
        // 1) ensure stage(s) landed (stage s+1 stays in flight)
        if (s + 1 < NSTAGE) cp_wait<1>(); else cp_wait<0>();
        // 2) publish stage(s); confirms buffer (s+2)%3 == (s-1)%3 consumed
        __syncthreads();
        // 3) refill the freed buffer
        if (s + 2 < NSTAGE) stage(s + 2, (s + 2) % 3);

        uint32_t base = sb + buf * BUFSZ;

        #pragma unroll
        for (int ks = 0; ks < 4; ++ks) {
            uint32_t x = (uint32_t)ks << 5;
            uint32_t ah[4][4], bh[2][4];
            #pragma unroll
            for (int mi = 0; mi < 4; ++mi)
                ldsm4(ah[mi], base + (offA[mi] ^ x));
            #pragma unroll
            for (int n2 = 0; n2 < 2; ++n2)
                ldsm4(bh[n2], base + OFF_BH + (offB[n2] ^ x));

            if (path == 0) {
                #pragma unroll
                for (int mi = 0; mi < 4; ++mi)
                    #pragma unroll
                    for (int n2 = 0; n2 < 2; ++n2) {
                        MMAH(acc[mi][2*n2],   ah[mi], bh[n2][0], bh[n2][1]);
                        MMAH(acc[mi][2*n2+1], ah[mi], bh[n2][2], bh[n2][3]);
                    }
            } else {
                #pragma unroll
                for (int mi = 0; mi < 4; ++mi)
                    #pragma unroll
                    for (int n2 = 0; n2 < 2; ++n2) {
                        MMAB(acc[mi][2*n2],   ah[mi], bh[n2][0], bh[n2][1]);
                        MMAB(acc[mi][2*n2+1], ah[mi], bh[n2][2], bh[n2][3]);
                    }
            }
        }
    }
    __syncthreads();

    // ---- epilogue: transpose via SMEM, coalesced float4 stores ----
    float* eps = (float*)smem;                 // [n=128][m pitch 132]
    #pragma unroll
    for (int mi = 0; mi < 4; ++mi) {
        int m0 = warp_m * 64 + mi * 16 + (lane >> 2);
        #pragma unroll
        for (int ni = 0; ni < 4; ++ni) {
            int n0 = warp_n * 32 + ni * 8 + 2 * (lane & 3);
            eps[n0 * 132 + m0]           = acc[mi][ni][0];
            eps[(n0 + 1) * 132 + m0]     = acc[mi][ni][1];
            eps[n0 * 132 + m0 + 8]       = acc[mi][ni][2];
            eps[(n0 + 1) * 132 + m0 + 8] = acc[mi][ni][3];
        }
    }
    __syncthreads();

    int pix0 = ptile * 128;
    int m = lane * 4;
    bool ok = (pix0 + m) < HW_OUT;
    if (path == 0) {
        #pragma unroll 1
        for (int rr = 0; rr < 16; ++rr) {
            int r = rr * 8 + wid;
            int o = og * 128 + r;
            float4 v = *(float4*)&eps[r * 132 + m];
            float bz = bias[o];
            v.x += bz; v.y += bz; v.z += bz; v.w += bz;
            if (ok)
                *(float4*)&out[((size_t)(b * O_ + o)) * HW_OUT + pix0 + m] = v;
        }
    } else {
        float* out2 = out + (size_t)B_ * O_ * HW_OUT;
        float4 sv = make_float4(0.f, 0.f, 0.f, 0.f);
        if (ok) sv = *(float4*)&g_S[(size_t)b * HW_OUT + pix0 + m];
        #pragma unroll 1
        for (int rr = 0; rr < 16; ++rr) {
            int r = rr * 8 + wid;
            int o = og * 128 + r;
            float4 v = *(float4*)&eps[r * 132 + m];
            float sp = g_sp[o];
            v.x = (sp * sv.x + v.x) * 0.001f;
            v.y = (sp * sv.y + v.y) * 0.001f;
            v.z = (sp * sv.z + v.z) * 0.001f;
            v.w = (sp * sv.w + v.w) * 0.001f;
            if (ok)
                *(float4*)&out2[((size_t)(b * O_ + o)) * HW_OUT + pix0 + m] = v;
        }
    }
}

// ---------------------------------------------------------------------------
extern "C" void kernel_launch(void* const* d_in, const int* in_sizes, int n_in,
                              void* d_out, int out_size) {
    const float* mu_x    = (const float*)d_in[0];
    const float* sigma_x = (const float*)d_in[1];
    const float* W       = (const float*)d_in[2];
    const float* bias    = (const float*)d_in[3];
    const float* w_sigma = (const float*)d_in[4];
    float* out = (float*)d_out;

    cudaFuncSetAttribute(mma_conv_kernel,
                         cudaFuncAttributeMaxDynamicSharedMemorySize, SMEM_MAIN);

    {
        dim3 g(HW_IN / 64, B_, 2);                 // 144 x 16 x 2
        transpose_split_kernel<<<g, 256>>>(mu_x, sigma_x);
    }
    wprep_kernel<<<(O_ * C_ + 255) / 256, 256>>>(W, w_sigma);
    {
        int n = B_ * HW_OUT;
        boxsum_kernel<<<(n + 255) / 256, 256>>>();
    }
    {
        dim3 grid(NPT, B_, 4);                     // 67 x 16 x 4 = 4288 CTAs
        mma_conv_kernel<<<grid, 256, SMEM_MAIN>>>(bias, out);
    }
}